// round 6
// baseline (speedup 1.0000x reference)
#include <cuda_runtime.h>

#define C_CH   128
#define NGROUP 32
#define CPG    4
#define BMAX   64
#define EPSF   1e-5f

// Scratch (no allocations allowed)
__device__ double g_sum[BMAX * C_CH];
__device__ double g_sqs[BMAX * C_CH];
__device__ int    g_bounds[BMAX + 1];
__device__ int    g_nseg;
__device__ float4 g_scale[BMAX * NGROUP];
__device__ float4 g_shift[BMAX * NGROUP];

// ---------------------------------------------------------------------------
// 0) setup: zero accumulators + segment bounds by binary search.
// ---------------------------------------------------------------------------
__global__ void dogn_setup(const int* __restrict__ bid, int n,
                           const int* __restrict__ bsz_ptr) {
    if (blockIdx.x < 16) {
        int i = blockIdx.x * 512 + threadIdx.x;
        if (i < BMAX * C_CH) {
            g_sum[i] = 0.0;
            g_sqs[i] = 0.0;
        }
    } else {
        int B = __ldg(bsz_ptr);
        if (B > BMAX) B = BMAX;
        int t = threadIdx.x;
        if (t == 0) g_nseg = B;
        if (t <= B) {
            int lo = 0, hi = n;
            while (lo < hi) {
                int mid = (lo + hi) >> 1;
                if (__ldg(&bid[mid]) < t) lo = mid + 1;
                else hi = mid;
            }
            g_bounds[t] = lo;
        }
    }
}

// ---------------------------------------------------------------------------
// 1) stats: block owns a SMALL contiguous row chunk (multi-wave grid to kill
//    the slow-CTA spread); per overlapping segment a pure ldcs->FMA stream
//    (4-row unroll), one atomic flush per (block, segment).
// ---------------------------------------------------------------------------
#define ACC4(v)                                   \
    s0 += (v).x; q0 = fmaf((v).x, (v).x, q0);     \
    s1 += (v).y; q1 = fmaf((v).y, (v).y, q1);     \
    s2 += (v).z; q2 = fmaf((v).z, (v).z, q2);     \
    s3 += (v).w; q3 = fmaf((v).w, (v).w, q3);

__global__ void dogn_stats(const float4* __restrict__ data,
                           int n, int rows_per_block) {
    __shared__ int sb[BMAX + 1];
    __shared__ int sB;
    if (threadIdx.x == 0) sB = g_nseg;
    __syncthreads();
    int B = sB;
    for (int j = threadIdx.x; j <= B; j += blockDim.x) sb[j] = g_bounds[j];
    __syncthreads();

    const int lane = threadIdx.x & 31;
    const int rsub = threadIdx.x >> 5;
    int r0 = blockIdx.x * rows_per_block;
    int r1 = r0 + rows_per_block;
    if (r1 > n) r1 = n;
    if (r0 >= r1) return;

    for (int seg = 0; seg < B; seg++) {
        int a = sb[seg], e = sb[seg + 1];
        if (a < r0) a = r0;
        if (e > r1) e = r1;
        if (a >= e) continue;

        float s0 = 0.f, s1 = 0.f, s2 = 0.f, s3 = 0.f;
        float q0 = 0.f, q1 = 0.f, q2 = 0.f, q3 = 0.f;

        int r = a + rsub;
        for (; r + 24 < e; r += 32) {
            const float4* p = &data[(size_t)r * 32 + lane];
            float4 v0 = __ldcs(p);
            float4 v1 = __ldcs(p + 8 * 32);
            float4 v2 = __ldcs(p + 16 * 32);
            float4 v3 = __ldcs(p + 24 * 32);
            ACC4(v0) ACC4(v1) ACC4(v2) ACC4(v3)
        }
        for (; r < e; r += 8) {
            float4 v = __ldcs(&data[(size_t)r * 32 + lane]);
            ACC4(v)
        }

        double* ps = &g_sum[seg * C_CH + lane * 4];
        double* pq = &g_sqs[seg * C_CH + lane * 4];
        atomicAdd(ps + 0, (double)s0);
        atomicAdd(ps + 1, (double)s1);
        atomicAdd(ps + 2, (double)s2);
        atomicAdd(ps + 3, (double)s3);
        atomicAdd(pq + 0, (double)q0);
        atomicAdd(pq + 1, (double)q1);
        atomicAdd(pq + 2, (double)q2);
        atomicAdd(pq + 3, (double)q3);
    }
}

// ---------------------------------------------------------------------------
// 2) finalize: one block per batch, 32 threads = 32 groups.
// ---------------------------------------------------------------------------
__global__ void dogn_finalize(const float* __restrict__ w,
                              const float* __restrict__ bias) {
    int b = blockIdx.x;
    if (b >= g_nseg) return;
    int g = threadIdx.x;

    int nb = g_bounds[b + 1] - g_bounds[b];
    double ic = 1.0 / (4.0 * (double)nb + (double)EPSF);

    double T1 = 0.0, T2 = 0.0;
#pragma unroll
    for (int k = 0; k < 4; k++) {
        T1 += g_sum[b * C_CH + g * 4 + k];
        T2 += g_sqs[b * C_CH + g * 4 + k];
    }
    double m   = T1 * ic;
    double var = (T2 - 2.0 * m * T1 + 4.0 * (double)nb * m * m) * ic;
    double is  = 1.0 / sqrt(var + (double)EPSF);

    float4 sc, sh;
    float wv, bv;
    wv = __ldg(&w[g * 4 + 0]); bv = __ldg(&bias[g * 4 + 0]);
    sc.x = (float)(is * wv);   sh.x = (float)(bv - m * is * wv);
    wv = __ldg(&w[g * 4 + 1]); bv = __ldg(&bias[g * 4 + 1]);
    sc.y = (float)(is * wv);   sh.y = (float)(bv - m * is * wv);
    wv = __ldg(&w[g * 4 + 2]); bv = __ldg(&bias[g * 4 + 2]);
    sc.z = (float)(is * wv);   sh.z = (float)(bv - m * is * wv);
    wv = __ldg(&w[g * 4 + 3]); bv = __ldg(&bias[g * 4 + 3]);
    sc.w = (float)(is * wv);   sh.w = (float)(bv - m * is * wv);

    g_scale[b * NGROUP + g] = sc;
    g_shift[b * NGROUP + g] = sh;
}

// ---------------------------------------------------------------------------
// 3) normalize: identical to R3 best — scale/shift in registers,
//    pure ldcs -> FFMA -> stcs stream, ascending rows.
// ---------------------------------------------------------------------------
__global__ void dogn_norm(const float4* __restrict__ data,
                          float4* __restrict__ out,
                          int n, int rows_per_block) {
    __shared__ int sb[BMAX + 1];
    __shared__ int sB;
    if (threadIdx.x == 0) sB = g_nseg;
    __syncthreads();
    int B = sB;
    for (int j = threadIdx.x; j <= B; j += blockDim.x) sb[j] = g_bounds[j];
    __syncthreads();

    const int lane = threadIdx.x & 31;
    const int rsub = threadIdx.x >> 5;
    int r0 = blockIdx.x * rows_per_block;
    int r1 = r0 + rows_per_block;
    if (r1 > n) r1 = n;
    if (r0 >= r1) return;

    for (int seg = 0; seg < B; seg++) {
        int a = sb[seg], e = sb[seg + 1];
        if (a < r0) a = r0;
        if (e > r1) e = r1;
        if (a >= e) continue;

        float4 sc = g_scale[seg * NGROUP + lane];
        float4 sh = g_shift[seg * NGROUP + lane];

        int r = a + rsub;
        for (; r + 24 < e; r += 32) {
            const float4* p = &data[(size_t)r * 32 + lane];
            float4* o = &out[(size_t)r * 32 + lane];
            float4 v0 = __ldcs(p);
            float4 v1 = __ldcs(p + 8 * 32);
            float4 v2 = __ldcs(p + 16 * 32);
            float4 v3 = __ldcs(p + 24 * 32);
            v0.x = fmaf(v0.x, sc.x, sh.x);
            v0.y = fmaf(v0.y, sc.y, sh.y);
            v0.z = fmaf(v0.z, sc.z, sh.z);
            v0.w = fmaf(v0.w, sc.w, sh.w);
            v1.x = fmaf(v1.x, sc.x, sh.x);
            v1.y = fmaf(v1.y, sc.y, sh.y);
            v1.z = fmaf(v1.z, sc.z, sh.z);
            v1.w = fmaf(v1.w, sc.w, sh.w);
            v2.x = fmaf(v2.x, sc.x, sh.x);
            v2.y = fmaf(v2.y, sc.y, sh.y);
            v2.z = fmaf(v2.z, sc.z, sh.z);
            v2.w = fmaf(v2.w, sc.w, sh.w);
            v3.x = fmaf(v3.x, sc.x, sh.x);
            v3.y = fmaf(v3.y, sc.y, sh.y);
            v3.z = fmaf(v3.z, sc.z, sh.z);
            v3.w = fmaf(v3.w, sc.w, sh.w);
            __stcs(o, v0);
            __stcs(o + 8 * 32, v1);
            __stcs(o + 16 * 32, v2);
            __stcs(o + 24 * 32, v3);
        }
        for (; r < e; r += 8) {
            float4 v = __ldcs(&data[(size_t)r * 32 + lane]);
            v.x = fmaf(v.x, sc.x, sh.x);
            v.y = fmaf(v.y, sc.y, sh.y);
            v.z = fmaf(v.z, sc.z, sh.z);
            v.w = fmaf(v.w, sc.w, sh.w);
            __stcs(&out[(size_t)r * 32 + lane], v);
        }
    }
}

// ---------------------------------------------------------------------------
extern "C" void kernel_launch(void* const* d_in, const int* in_sizes, int n_in,
                              void* d_out, int out_size) {
    const float* data = (const float*)d_in[0];
    const float* w    = (const float*)d_in[1];
    const float* bias = (const float*)d_in[2];
    const int*   bid  = (const int*)d_in[3];
    const int*   bsz  = (const int*)d_in[4];

    int n = in_sizes[0] / C_CH;   // rows

    dogn_setup<<<17, 512>>>(bid, n, bsz);

    // stats: fine-grained multi-wave grid to absorb the slow-CTA spread
    const int SGRID = 4736;
    int srpb = (n + SGRID - 1) / SGRID;
    dogn_stats<<<SGRID, 256>>>((const float4*)data, n, srpb);

    dogn_finalize<<<BMAX, 32>>>(w, bias);

    // norm: unchanged from best (R3)
    const int NGRID = 1184;
    int nrpb = (n + NGRID - 1) / NGRID;
    dogn_norm<<<NGRID, 256>>>((const float4*)data, (float4*)d_out, n, nrpb);
}

// round 7
// speedup vs baseline: 1.7767x; 1.7767x over previous
#include <cuda_runtime.h>

#define C_CH   128
#define NGROUP 32
#define CPG    4
#define BMAX   64
#define EPSF   1e-5f

// Scratch (no allocations allowed)
__device__ double g_sum[BMAX * C_CH];
__device__ double g_sqs[BMAX * C_CH];
__device__ int    g_bounds[BMAX + 1];
__device__ int    g_nseg;
__device__ float4 g_scale[BMAX * NGROUP];
__device__ float4 g_shift[BMAX * NGROUP];

// ---------------------------------------------------------------------------
// 0) setup: zero accumulators + segment bounds by binary search.
// ---------------------------------------------------------------------------
__global__ void dogn_setup(const int* __restrict__ bid, int n,
                           const int* __restrict__ bsz_ptr) {
    if (blockIdx.x < 16) {
        int i = blockIdx.x * 512 + threadIdx.x;
        if (i < BMAX * C_CH) {
            g_sum[i] = 0.0;
            g_sqs[i] = 0.0;
        }
    } else {
        int B = __ldg(bsz_ptr);
        if (B > BMAX) B = BMAX;
        int t = threadIdx.x;
        if (t == 0) g_nseg = B;
        if (t <= B) {
            int lo = 0, hi = n;
            while (lo < hi) {
                int mid = (lo + hi) >> 1;
                if (__ldg(&bid[mid]) < t) lo = mid + 1;
                else hi = mid;
            }
            g_bounds[t] = lo;
        }
    }
}

// ---------------------------------------------------------------------------
// 1) stats: block owns a contiguous row chunk (GRID=1184, proven); per
//    overlapping segment a pure ldcs->FMA stream (4-row unroll). Flush via
//    cross-warp smem reduction: warp 0 issues 256 atomics per block-segment
//    instead of 2048.
// ---------------------------------------------------------------------------
#define ACC4(v)                                   \
    s0 += (v).x; q0 = fmaf((v).x, (v).x, q0);     \
    s1 += (v).y; q1 = fmaf((v).y, (v).y, q1);     \
    s2 += (v).z; q2 = fmaf((v).z, (v).z, q2);     \
    s3 += (v).w; q3 = fmaf((v).w, (v).w, q3);

__global__ void dogn_stats(const float4* __restrict__ data,
                           int n, int rows_per_block) {
    __shared__ int   sb[BMAX + 1];
    __shared__ int   sB;
    __shared__ float red[8 * 256];   // [k][warp*32 + lane]

    if (threadIdx.x == 0) sB = g_nseg;
    __syncthreads();
    int B = sB;
    for (int j = threadIdx.x; j <= B; j += blockDim.x) sb[j] = g_bounds[j];
    __syncthreads();

    const int tid  = threadIdx.x;
    const int lane = tid & 31;
    const int rsub = tid >> 5;
    int r0 = blockIdx.x * rows_per_block;
    int r1 = r0 + rows_per_block;
    if (r1 > n) r1 = n;
    // NOTE: do not early-return; segment loop must stay block-uniform for
    // the __syncthreads below. Blocks with empty range just fall through.

    for (int seg = 0; seg < B; seg++) {
        int a = sb[seg], e = sb[seg + 1];
        if (a < r0) a = r0;
        if (e > r1) e = r1;
        if (a >= e) continue;   // block-uniform condition (a,e uniform)

        float s0 = 0.f, s1 = 0.f, s2 = 0.f, s3 = 0.f;
        float q0 = 0.f, q1 = 0.f, q2 = 0.f, q3 = 0.f;

        int r = a + rsub;
        for (; r + 24 < e; r += 32) {
            const float4* p = &data[(size_t)r * 32 + lane];
            float4 v0 = __ldcs(p);
            float4 v1 = __ldcs(p + 8 * 32);
            float4 v2 = __ldcs(p + 16 * 32);
            float4 v3 = __ldcs(p + 24 * 32);
            ACC4(v0) ACC4(v1) ACC4(v2) ACC4(v3)
        }
        for (; r < e; r += 8) {
            float4 v = __ldcs(&data[(size_t)r * 32 + lane]);
            ACC4(v)
        }

        // cross-warp reduction in smem, then warp 0 flushes
        red[0 * 256 + tid] = s0;
        red[1 * 256 + tid] = s1;
        red[2 * 256 + tid] = s2;
        red[3 * 256 + tid] = s3;
        red[4 * 256 + tid] = q0;
        red[5 * 256 + tid] = q1;
        red[6 * 256 + tid] = q2;
        red[7 * 256 + tid] = q3;
        __syncthreads();

        if (tid < 32) {
            double* ps = &g_sum[seg * C_CH + tid * 4];
            double* pq = &g_sqs[seg * C_CH + tid * 4];
#pragma unroll
            for (int k = 0; k < 4; k++) {
                float vs = 0.f, vq = 0.f;
#pragma unroll
                for (int w = 0; w < 8; w++) {
                    vs += red[k * 256 + w * 32 + tid];
                    vq += red[(k + 4) * 256 + w * 32 + tid];
                }
                atomicAdd(ps + k, (double)vs);
                atomicAdd(pq + k, (double)vq);
            }
        }
        __syncthreads();   // red reused next segment
    }
}

// ---------------------------------------------------------------------------
// 2) finalize: one block per batch, 32 threads = 32 groups.
// ---------------------------------------------------------------------------
__global__ void dogn_finalize(const float* __restrict__ w,
                              const float* __restrict__ bias) {
    int b = blockIdx.x;
    if (b >= g_nseg) return;
    int g = threadIdx.x;

    int nb = g_bounds[b + 1] - g_bounds[b];
    double ic = 1.0 / (4.0 * (double)nb + (double)EPSF);

    double T1 = 0.0, T2 = 0.0;
#pragma unroll
    for (int k = 0; k < 4; k++) {
        T1 += g_sum[b * C_CH + g * 4 + k];
        T2 += g_sqs[b * C_CH + g * 4 + k];
    }
    double m   = T1 * ic;
    double var = (T2 - 2.0 * m * T1 + 4.0 * (double)nb * m * m) * ic;
    double is  = 1.0 / sqrt(var + (double)EPSF);

    float4 sc, sh;
    float wv, bv;
    wv = __ldg(&w[g * 4 + 0]); bv = __ldg(&bias[g * 4 + 0]);
    sc.x = (float)(is * wv);   sh.x = (float)(bv - m * is * wv);
    wv = __ldg(&w[g * 4 + 1]); bv = __ldg(&bias[g * 4 + 1]);
    sc.y = (float)(is * wv);   sh.y = (float)(bv - m * is * wv);
    wv = __ldg(&w[g * 4 + 2]); bv = __ldg(&bias[g * 4 + 2]);
    sc.z = (float)(is * wv);   sh.z = (float)(bv - m * is * wv);
    wv = __ldg(&w[g * 4 + 3]); bv = __ldg(&bias[g * 4 + 3]);
    sc.w = (float)(is * wv);   sh.w = (float)(bv - m * is * wv);

    g_scale[b * NGROUP + g] = sc;
    g_shift[b * NGROUP + g] = sh;
}

// ---------------------------------------------------------------------------
// 3) normalize: identical to R3 best — scale/shift in registers,
//    pure ldcs -> FFMA -> stcs stream, ascending rows.
// ---------------------------------------------------------------------------
__global__ void dogn_norm(const float4* __restrict__ data,
                          float4* __restrict__ out,
                          int n, int rows_per_block) {
    __shared__ int sb[BMAX + 1];
    __shared__ int sB;
    if (threadIdx.x == 0) sB = g_nseg;
    __syncthreads();
    int B = sB;
    for (int j = threadIdx.x; j <= B; j += blockDim.x) sb[j] = g_bounds[j];
    __syncthreads();

    const int lane = threadIdx.x & 31;
    const int rsub = threadIdx.x >> 5;
    int r0 = blockIdx.x * rows_per_block;
    int r1 = r0 + rows_per_block;
    if (r1 > n) r1 = n;
    if (r0 >= r1) return;

    for (int seg = 0; seg < B; seg++) {
        int a = sb[seg], e = sb[seg + 1];
        if (a < r0) a = r0;
        if (e > r1) e = r1;
        if (a >= e) continue;

        float4 sc = g_scale[seg * NGROUP + lane];
        float4 sh = g_shift[seg * NGROUP + lane];

        int r = a + rsub;
        for (; r + 24 < e; r += 32) {
            const float4* p = &data[(size_t)r * 32 + lane];
            float4* o = &out[(size_t)r * 32 + lane];
            float4 v0 = __ldcs(p);
            float4 v1 = __ldcs(p + 8 * 32);
            float4 v2 = __ldcs(p + 16 * 32);
            float4 v3 = __ldcs(p + 24 * 32);
            v0.x = fmaf(v0.x, sc.x, sh.x);
            v0.y = fmaf(v0.y, sc.y, sh.y);
            v0.z = fmaf(v0.z, sc.z, sh.z);
            v0.w = fmaf(v0.w, sc.w, sh.w);
            v1.x = fmaf(v1.x, sc.x, sh.x);
            v1.y = fmaf(v1.y, sc.y, sh.y);
            v1.z = fmaf(v1.z, sc.z, sh.z);
            v1.w = fmaf(v1.w, sc.w, sh.w);
            v2.x = fmaf(v2.x, sc.x, sh.x);
            v2.y = fmaf(v2.y, sc.y, sh.y);
            v2.z = fmaf(v2.z, sc.z, sh.z);
            v2.w = fmaf(v2.w, sc.w, sh.w);
            v3.x = fmaf(v3.x, sc.x, sh.x);
            v3.y = fmaf(v3.y, sc.y, sh.y);
            v3.z = fmaf(v3.z, sc.z, sh.z);
            v3.w = fmaf(v3.w, sc.w, sh.w);
            __stcs(o, v0);
            __stcs(o + 8 * 32, v1);
            __stcs(o + 16 * 32, v2);
            __stcs(o + 24 * 32, v3);
        }
        for (; r < e; r += 8) {
            float4 v = __ldcs(&data[(size_t)r * 32 + lane]);
            v.x = fmaf(v.x, sc.x, sh.x);
            v.y = fmaf(v.y, sc.y, sh.y);
            v.z = fmaf(v.z, sc.z, sh.z);
            v.w = fmaf(v.w, sc.w, sh.w);
            __stcs(&out[(size_t)r * 32 + lane], v);
        }
    }
}

// ---------------------------------------------------------------------------
extern "C" void kernel_launch(void* const* d_in, const int* in_sizes, int n_in,
                              void* d_out, int out_size) {
    const float* data = (const float*)d_in[0];
    const float* w    = (const float*)d_in[1];
    const float* bias = (const float*)d_in[2];
    const int*   bid  = (const int*)d_in[3];
    const int*   bsz  = (const int*)d_in[4];

    int n = in_sizes[0] / C_CH;   // rows

    dogn_setup<<<17, 512>>>(bid, n, bsz);

    const int GRID = 1184;
    int rpb = (n + GRID - 1) / GRID;
    dogn_stats<<<GRID, 256>>>((const float4*)data, n, rpb);

    dogn_finalize<<<BMAX, 32>>>(w, bias);

    dogn_norm<<<GRID, 256>>>((const float4*)data, (float4*)d_out, n, rpb);
}

// round 8
// speedup vs baseline: 1.7919x; 1.0085x over previous
#include <cuda_runtime.h>

#define C_CH   128
#define NGROUP 32
#define CPG    4
#define BMAX   64
#define EPSF   1e-5f

// Scratch (no allocations allowed)
__device__ double g_sum[BMAX * C_CH];
__device__ double g_sqs[BMAX * C_CH];
__device__ int    g_bounds[BMAX + 1];
__device__ int    g_nseg;
__device__ float4 g_scale[BMAX * NGROUP];
__device__ float4 g_shift[BMAX * NGROUP];

// ---------------------------------------------------------------------------
// 0) setup: zero accumulators + segment bounds by binary search.
// ---------------------------------------------------------------------------
__global__ void dogn_setup(const int* __restrict__ bid, int n,
                           const int* __restrict__ bsz_ptr) {
    if (blockIdx.x < 16) {
        int i = blockIdx.x * 512 + threadIdx.x;
        if (i < BMAX * C_CH) {
            g_sum[i] = 0.0;
            g_sqs[i] = 0.0;
        }
    } else {
        int B = __ldg(bsz_ptr);
        if (B > BMAX) B = BMAX;
        int t = threadIdx.x;
        if (t == 0) g_nseg = B;
        if (t <= B) {
            int lo = 0, hi = n;
            while (lo < hi) {
                int mid = (lo + hi) >> 1;
                if (__ldg(&bid[mid]) < t) lo = mid + 1;
                else hi = mid;
            }
            g_bounds[t] = lo;
        }
    }
}

// ---------------------------------------------------------------------------
// 1) stats (unchanged from R7 WIN): block owns contiguous row chunk;
//    per overlapping segment a pure ldcs->FMA stream (4-row unroll);
//    flush via cross-warp smem reduction, warp 0 issues the atomics.
// ---------------------------------------------------------------------------
#define ACC4(v)                                   \
    s0 += (v).x; q0 = fmaf((v).x, (v).x, q0);     \
    s1 += (v).y; q1 = fmaf((v).y, (v).y, q1);     \
    s2 += (v).z; q2 = fmaf((v).z, (v).z, q2);     \
    s3 += (v).w; q3 = fmaf((v).w, (v).w, q3);

__global__ void dogn_stats(const float4* __restrict__ data,
                           int n, int rows_per_block) {
    __shared__ int   sb[BMAX + 1];
    __shared__ int   sB;
    __shared__ float red[8 * 256];   // [k][warp*32 + lane]

    if (threadIdx.x == 0) sB = g_nseg;
    __syncthreads();
    int B = sB;
    for (int j = threadIdx.x; j <= B; j += blockDim.x) sb[j] = g_bounds[j];
    __syncthreads();

    const int tid  = threadIdx.x;
    const int lane = tid & 31;
    const int rsub = tid >> 5;
    int r0 = blockIdx.x * rows_per_block;
    int r1 = r0 + rows_per_block;
    if (r1 > n) r1 = n;
    // No early-return: segment loop stays block-uniform for __syncthreads.

    for (int seg = 0; seg < B; seg++) {
        int a = sb[seg], e = sb[seg + 1];
        if (a < r0) a = r0;
        if (e > r1) e = r1;
        if (a >= e) continue;   // block-uniform

        float s0 = 0.f, s1 = 0.f, s2 = 0.f, s3 = 0.f;
        float q0 = 0.f, q1 = 0.f, q2 = 0.f, q3 = 0.f;

        int r = a + rsub;
        for (; r + 24 < e; r += 32) {
            const float4* p = &data[(size_t)r * 32 + lane];
            float4 v0 = __ldcs(p);
            float4 v1 = __ldcs(p + 8 * 32);
            float4 v2 = __ldcs(p + 16 * 32);
            float4 v3 = __ldcs(p + 24 * 32);
            ACC4(v0) ACC4(v1) ACC4(v2) ACC4(v3)
        }
        for (; r < e; r += 8) {
            float4 v = __ldcs(&data[(size_t)r * 32 + lane]);
            ACC4(v)
        }

        red[0 * 256 + tid] = s0;
        red[1 * 256 + tid] = s1;
        red[2 * 256 + tid] = s2;
        red[3 * 256 + tid] = s3;
        red[4 * 256 + tid] = q0;
        red[5 * 256 + tid] = q1;
        red[6 * 256 + tid] = q2;
        red[7 * 256 + tid] = q3;
        __syncthreads();

        if (tid < 32) {
            double* ps = &g_sum[seg * C_CH + tid * 4];
            double* pq = &g_sqs[seg * C_CH + tid * 4];
#pragma unroll
            for (int k = 0; k < 4; k++) {
                float vs = 0.f, vq = 0.f;
#pragma unroll
                for (int w = 0; w < 8; w++) {
                    vs += red[k * 256 + w * 32 + tid];
                    vq += red[(k + 4) * 256 + w * 32 + tid];
                }
                atomicAdd(ps + k, (double)vs);
                atomicAdd(pq + k, (double)vq);
            }
        }
        __syncthreads();
    }
}

// ---------------------------------------------------------------------------
// 2) finalize: one block per batch, 32 threads = 32 groups.
// ---------------------------------------------------------------------------
__global__ void dogn_finalize(const float* __restrict__ w,
                              const float* __restrict__ bias) {
    int b = blockIdx.x;
    if (b >= g_nseg) return;
    int g = threadIdx.x;

    int nb = g_bounds[b + 1] - g_bounds[b];
    double ic = 1.0 / (4.0 * (double)nb + (double)EPSF);

    double T1 = 0.0, T2 = 0.0;
#pragma unroll
    for (int k = 0; k < 4; k++) {
        T1 += g_sum[b * C_CH + g * 4 + k];
        T2 += g_sqs[b * C_CH + g * 4 + k];
    }
    double m   = T1 * ic;
    double var = (T2 - 2.0 * m * T1 + 4.0 * (double)nb * m * m) * ic;
    double is  = 1.0 / sqrt(var + (double)EPSF);

    float4 sc, sh;
    float wv, bv;
    wv = __ldg(&w[g * 4 + 0]); bv = __ldg(&bias[g * 4 + 0]);
    sc.x = (float)(is * wv);   sh.x = (float)(bv - m * is * wv);
    wv = __ldg(&w[g * 4 + 1]); bv = __ldg(&bias[g * 4 + 1]);
    sc.y = (float)(is * wv);   sh.y = (float)(bv - m * is * wv);
    wv = __ldg(&w[g * 4 + 2]); bv = __ldg(&bias[g * 4 + 2]);
    sc.z = (float)(is * wv);   sh.z = (float)(bv - m * is * wv);
    wv = __ldg(&w[g * 4 + 3]); bv = __ldg(&bias[g * 4 + 3]);
    sc.w = (float)(is * wv);   sh.w = (float)(bv - m * is * wv);

    g_scale[b * NGROUP + g] = sc;
    g_shift[b * NGROUP + g] = sh;
}

// ---------------------------------------------------------------------------
// 3) normalize: EXACT R3 body (inline index arithmetic — measured-fastest
//    register allocation) + launch_bounds giving ptxas a 64-reg budget.
// ---------------------------------------------------------------------------
__global__ void __launch_bounds__(256, 4)
dogn_norm(const float4* __restrict__ data,
          float4* __restrict__ out,
          int n, int rows_per_block) {
    __shared__ int sb[BMAX + 1];
    __shared__ int sB;
    if (threadIdx.x == 0) sB = g_nseg;
    __syncthreads();
    int B = sB;
    for (int j = threadIdx.x; j <= B; j += blockDim.x) sb[j] = g_bounds[j];
    __syncthreads();

    const int lane = threadIdx.x & 31;
    const int rsub = threadIdx.x >> 5;
    int r0 = blockIdx.x * rows_per_block;
    int r1 = r0 + rows_per_block;
    if (r1 > n) r1 = n;
    if (r0 >= r1) return;

    for (int seg = 0; seg < B; seg++) {
        int a = sb[seg], e = sb[seg + 1];
        if (a < r0) a = r0;
        if (e > r1) e = r1;
        if (a >= e) continue;

        float4 sc = g_scale[seg * NGROUP + lane];
        float4 sh = g_shift[seg * NGROUP + lane];

        int r = a + rsub;
        for (; r + 24 < e; r += 32) {
            float4 v0 = __ldcs(&data[(size_t)r * 32 + lane]);
            float4 v1 = __ldcs(&data[(size_t)(r + 8) * 32 + lane]);
            float4 v2 = __ldcs(&data[(size_t)(r + 16) * 32 + lane]);
            float4 v3 = __ldcs(&data[(size_t)(r + 24) * 32 + lane]);
            v0.x = fmaf(v0.x, sc.x, sh.x);
            v0.y = fmaf(v0.y, sc.y, sh.y);
            v0.z = fmaf(v0.z, sc.z, sh.z);
            v0.w = fmaf(v0.w, sc.w, sh.w);
            v1.x = fmaf(v1.x, sc.x, sh.x);
            v1.y = fmaf(v1.y, sc.y, sh.y);
            v1.z = fmaf(v1.z, sc.z, sh.z);
            v1.w = fmaf(v1.w, sc.w, sh.w);
            v2.x = fmaf(v2.x, sc.x, sh.x);
            v2.y = fmaf(v2.y, sc.y, sh.y);
            v2.z = fmaf(v2.z, sc.z, sh.z);
            v2.w = fmaf(v2.w, sc.w, sh.w);
            v3.x = fmaf(v3.x, sc.x, sh.x);
            v3.y = fmaf(v3.y, sc.y, sh.y);
            v3.z = fmaf(v3.z, sc.z, sh.z);
            v3.w = fmaf(v3.w, sc.w, sh.w);
            __stcs(&out[(size_t)r * 32 + lane], v0);
            __stcs(&out[(size_t)(r + 8) * 32 + lane], v1);
            __stcs(&out[(size_t)(r + 16) * 32 + lane], v2);
            __stcs(&out[(size_t)(r + 24) * 32 + lane], v3);
        }
        for (; r < e; r += 8) {
            float4 v = __ldcs(&data[(size_t)r * 32 + lane]);
            v.x = fmaf(v.x, sc.x, sh.x);
            v.y = fmaf(v.y, sc.y, sh.y);
            v.z = fmaf(v.z, sc.z, sh.z);
            v.w = fmaf(v.w, sc.w, sh.w);
            __stcs(&out[(size_t)r * 32 + lane], v);
        }
    }
}

// ---------------------------------------------------------------------------
extern "C" void kernel_launch(void* const* d_in, const int* in_sizes, int n_in,
                              void* d_out, int out_size) {
    const float* data = (const float*)d_in[0];
    const float* w    = (const float*)d_in[1];
    const float* bias = (const float*)d_in[2];
    const int*   bid  = (const int*)d_in[3];
    const int*   bsz  = (const int*)d_in[4];

    int n = in_sizes[0] / C_CH;   // rows

    dogn_setup<<<17, 512>>>(bid, n, bsz);

    const int GRID = 1184;
    int rpb = (n + GRID - 1) / GRID;
    dogn_stats<<<GRID, 256>>>((const float4*)data, n, rpb);

    dogn_finalize<<<BMAX, 32>>>(w, bias);

    dogn_norm<<<GRID, 256>>>((const float4*)data, (float4*)d_out, n, rpb);
}

// round 9
// speedup vs baseline: 1.8159x; 1.0134x over previous
#include <cuda_runtime.h>

#define C_CH   128
#define NGROUP 32
#define CPG    4
#define BMAX   64
#define EPSF   1e-5f

// Scratch (no allocations allowed)
__device__ double g_sum[BMAX * C_CH];
__device__ double g_sqs[BMAX * C_CH];
__device__ int    g_bounds[BMAX + 1];
__device__ int    g_nseg;
__device__ float4 g_scale[BMAX * NGROUP];
__device__ float4 g_shift[BMAX * NGROUP];

// ---------------------------------------------------------------------------
// 0) setup: zero accumulators + segment bounds by binary search.
// ---------------------------------------------------------------------------
__global__ void dogn_setup(const int* __restrict__ bid, int n,
                           const int* __restrict__ bsz_ptr) {
    if (blockIdx.x < 16) {
        int i = blockIdx.x * 512 + threadIdx.x;
        if (i < BMAX * C_CH) {
            g_sum[i] = 0.0;
            g_sqs[i] = 0.0;
        }
    } else {
        int B = __ldg(bsz_ptr);
        if (B > BMAX) B = BMAX;
        int t = threadIdx.x;
        if (t == 0) g_nseg = B;
        if (t <= B) {
            int lo = 0, hi = n;
            while (lo < hi) {
                int mid = (lo + hi) >> 1;
                if (__ldg(&bid[mid]) < t) lo = mid + 1;
                else hi = mid;
            }
            g_bounds[t] = lo;
        }
    }
}

// ---------------------------------------------------------------------------
// 1) stats (R7/R8 WIN form): block owns contiguous row chunk; per overlapping
//    segment a pure ldcs->FMA stream (4-row unroll); flush via cross-warp
//    smem reduction, warp 0 issues the atomics.
// ---------------------------------------------------------------------------
#define ACC4(v)                                   \
    s0 += (v).x; q0 = fmaf((v).x, (v).x, q0);     \
    s1 += (v).y; q1 = fmaf((v).y, (v).y, q1);     \
    s2 += (v).z; q2 = fmaf((v).z, (v).z, q2);     \
    s3 += (v).w; q3 = fmaf((v).w, (v).w, q3);

__global__ void dogn_stats(const float4* __restrict__ data,
                           int n, int rows_per_block) {
    __shared__ int   sb[BMAX + 1];
    __shared__ int   sB;
    __shared__ float red[8 * 256];   // [k][warp*32 + lane]

    if (threadIdx.x == 0) sB = g_nseg;
    __syncthreads();
    int B = sB;
    for (int j = threadIdx.x; j <= B; j += blockDim.x) sb[j] = g_bounds[j];
    __syncthreads();

    const int tid  = threadIdx.x;
    const int lane = tid & 31;
    const int rsub = tid >> 5;
    int r0 = blockIdx.x * rows_per_block;
    int r1 = r0 + rows_per_block;
    if (r1 > n) r1 = n;
    // No early-return: segment loop stays block-uniform for __syncthreads.

    for (int seg = 0; seg < B; seg++) {
        int a = sb[seg], e = sb[seg + 1];
        if (a < r0) a = r0;
        if (e > r1) e = r1;
        if (a >= e) continue;   // block-uniform

        float s0 = 0.f, s1 = 0.f, s2 = 0.f, s3 = 0.f;
        float q0 = 0.f, q1 = 0.f, q2 = 0.f, q3 = 0.f;

        int r = a + rsub;
        for (; r + 24 < e; r += 32) {
            const float4* p = &data[(size_t)r * 32 + lane];
            float4 v0 = __ldcs(p);
            float4 v1 = __ldcs(p + 8 * 32);
            float4 v2 = __ldcs(p + 16 * 32);
            float4 v3 = __ldcs(p + 24 * 32);
            ACC4(v0) ACC4(v1) ACC4(v2) ACC4(v3)
        }
        for (; r < e; r += 8) {
            float4 v = __ldcs(&data[(size_t)r * 32 + lane]);
            ACC4(v)
        }

        red[0 * 256 + tid] = s0;
        red[1 * 256 + tid] = s1;
        red[2 * 256 + tid] = s2;
        red[3 * 256 + tid] = s3;
        red[4 * 256 + tid] = q0;
        red[5 * 256 + tid] = q1;
        red[6 * 256 + tid] = q2;
        red[7 * 256 + tid] = q3;
        __syncthreads();

        if (tid < 32) {
            double* ps = &g_sum[seg * C_CH + tid * 4];
            double* pq = &g_sqs[seg * C_CH + tid * 4];
#pragma unroll
            for (int k = 0; k < 4; k++) {
                float vs = 0.f, vq = 0.f;
#pragma unroll
                for (int w = 0; w < 8; w++) {
                    vs += red[k * 256 + w * 32 + tid];
                    vq += red[(k + 4) * 256 + w * 32 + tid];
                }
                atomicAdd(ps + k, (double)vs);
                atomicAdd(pq + k, (double)vq);
            }
        }
        __syncthreads();
    }
}

// ---------------------------------------------------------------------------
// 2) finalize: one block per batch, 32 threads = 32 groups.
// ---------------------------------------------------------------------------
__global__ void dogn_finalize(const float* __restrict__ w,
                              const float* __restrict__ bias) {
    int b = blockIdx.x;
    if (b >= g_nseg) return;
    int g = threadIdx.x;

    int nb = g_bounds[b + 1] - g_bounds[b];
    double ic = 1.0 / (4.0 * (double)nb + (double)EPSF);

    double T1 = 0.0, T2 = 0.0;
#pragma unroll
    for (int k = 0; k < 4; k++) {
        T1 += g_sum[b * C_CH + g * 4 + k];
        T2 += g_sqs[b * C_CH + g * 4 + k];
    }
    double m   = T1 * ic;
    double var = (T2 - 2.0 * m * T1 + 4.0 * (double)nb * m * m) * ic;
    double is  = 1.0 / sqrt(var + (double)EPSF);

    float4 sc, sh;
    float wv, bv;
    wv = __ldg(&w[g * 4 + 0]); bv = __ldg(&bias[g * 4 + 0]);
    sc.x = (float)(is * wv);   sh.x = (float)(bv - m * is * wv);
    wv = __ldg(&w[g * 4 + 1]); bv = __ldg(&bias[g * 4 + 1]);
    sc.y = (float)(is * wv);   sh.y = (float)(bv - m * is * wv);
    wv = __ldg(&w[g * 4 + 2]); bv = __ldg(&bias[g * 4 + 2]);
    sc.z = (float)(is * wv);   sh.z = (float)(bv - m * is * wv);
    wv = __ldg(&w[g * 4 + 3]); bv = __ldg(&bias[g * 4 + 3]);
    sc.w = (float)(is * wv);   sh.w = (float)(bv - m * is * wv);

    g_scale[b * NGROUP + g] = sc;
    g_shift[b * NGROUP + g] = sh;
}

// ---------------------------------------------------------------------------
// 3) normalize: EXACT R3 body, NO launch bounds — the compilation environment
//    that produced the measured-fastest allocation (48 regs, 5 CTAs/SM).
// ---------------------------------------------------------------------------
__global__ void dogn_norm(const float4* __restrict__ data,
                          float4* __restrict__ out,
                          int n, int rows_per_block) {
    __shared__ int sb[BMAX + 1];
    __shared__ int sB;
    if (threadIdx.x == 0) sB = g_nseg;
    __syncthreads();
    int B = sB;
    for (int j = threadIdx.x; j <= B; j += blockDim.x) sb[j] = g_bounds[j];
    __syncthreads();

    const int lane = threadIdx.x & 31;
    const int rsub = threadIdx.x >> 5;
    int r0 = blockIdx.x * rows_per_block;
    int r1 = r0 + rows_per_block;
    if (r1 > n) r1 = n;
    if (r0 >= r1) return;

    for (int seg = 0; seg < B; seg++) {
        int a = sb[seg], e = sb[seg + 1];
        if (a < r0) a = r0;
        if (e > r1) e = r1;
        if (a >= e) continue;

        float4 sc = g_scale[seg * NGROUP + lane];
        float4 sh = g_shift[seg * NGROUP + lane];

        int r = a + rsub;
        for (; r + 24 < e; r += 32) {
            float4 v0 = __ldcs(&data[(size_t)r * 32 + lane]);
            float4 v1 = __ldcs(&data[(size_t)(r + 8) * 32 + lane]);
            float4 v2 = __ldcs(&data[(size_t)(r + 16) * 32 + lane]);
            float4 v3 = __ldcs(&data[(size_t)(r + 24) * 32 + lane]);
            v0.x = fmaf(v0.x, sc.x, sh.x);
            v0.y = fmaf(v0.y, sc.y, sh.y);
            v0.z = fmaf(v0.z, sc.z, sh.z);
            v0.w = fmaf(v0.w, sc.w, sh.w);
            v1.x = fmaf(v1.x, sc.x, sh.x);
            v1.y = fmaf(v1.y, sc.y, sh.y);
            v1.z = fmaf(v1.z, sc.z, sh.z);
            v1.w = fmaf(v1.w, sc.w, sh.w);
            v2.x = fmaf(v2.x, sc.x, sh.x);
            v2.y = fmaf(v2.y, sc.y, sh.y);
            v2.z = fmaf(v2.z, sc.z, sh.z);
            v2.w = fmaf(v2.w, sc.w, sh.w);
            v3.x = fmaf(v3.x, sc.x, sh.x);
            v3.y = fmaf(v3.y, sc.y, sh.y);
            v3.z = fmaf(v3.z, sc.z, sh.z);
            v3.w = fmaf(v3.w, sc.w, sh.w);
            __stcs(&out[(size_t)r * 32 + lane], v0);
            __stcs(&out[(size_t)(r + 8) * 32 + lane], v1);
            __stcs(&out[(size_t)(r + 16) * 32 + lane], v2);
            __stcs(&out[(size_t)(r + 24) * 32 + lane], v3);
        }
        for (; r < e; r += 8) {
            float4 v = __ldcs(&data[(size_t)r * 32 + lane]);
            v.x = fmaf(v.x, sc.x, sh.x);
            v.y = fmaf(v.y, sc.y, sh.y);
            v.z = fmaf(v.z, sc.z, sh.z);
            v.w = fmaf(v.w, sc.w, sh.w);
            __stcs(&out[(size_t)r * 32 + lane], v);
        }
    }
}

// ---------------------------------------------------------------------------
extern "C" void kernel_launch(void* const* d_in, const int* in_sizes, int n_in,
                              void* d_out, int out_size) {
    const float* data = (const float*)d_in[0];
    const float* w    = (const float*)d_in[1];
    const float* bias = (const float*)d_in[2];
    const int*   bid  = (const int*)d_in[3];
    const int*   bsz  = (const int*)d_in[4];

    int n = in_sizes[0] / C_CH;   // rows

    dogn_setup<<<17, 512>>>(bid, n, bsz);

    const int GRID = 1184;
    int rpb = (n + GRID - 1) / GRID;
    dogn_stats<<<GRID, 256>>>((const float4*)data, n, rpb);

    dogn_finalize<<<BMAX, 32>>>(w, bias);

    dogn_norm<<<GRID, 256>>>((const float4*)data, (float4*)d_out, n, rpb);
}

// round 10
// speedup vs baseline: 1.8285x; 1.0069x over previous
#include <cuda_runtime.h>

#define C_CH   128
#define NGROUP 32
#define CPG    4
#define BMAX   64
#define EPSF   1e-5f

// Scratch (no allocations allowed)
__device__ double g_sum[BMAX * C_CH];
__device__ double g_sqs[BMAX * C_CH];
__device__ int    g_bounds[BMAX + 1];
__device__ int    g_nseg;
__device__ float4 g_scale[BMAX * NGROUP];
__device__ float4 g_shift[BMAX * NGROUP];

// ---------------------------------------------------------------------------
// 0) setup: zero accumulators + segment bounds by binary search.
// ---------------------------------------------------------------------------
__global__ void dogn_setup(const int* __restrict__ bid, int n,
                           const int* __restrict__ bsz_ptr) {
    if (blockIdx.x < 16) {
        int i = blockIdx.x * 512 + threadIdx.x;
        if (i < BMAX * C_CH) {
            g_sum[i] = 0.0;
            g_sqs[i] = 0.0;
        }
    } else {
        int B = __ldg(bsz_ptr);
        if (B > BMAX) B = BMAX;
        int t = threadIdx.x;
        if (t == 0) g_nseg = B;
        if (t <= B) {
            int lo = 0, hi = n;
            while (lo < hi) {
                int mid = (lo + hi) >> 1;
                if (__ldg(&bid[mid]) < t) lo = mid + 1;
                else hi = mid;
            }
            g_bounds[t] = lo;
        }
    }
}

// ---------------------------------------------------------------------------
// 1) stats (R7 WIN form, finer grid): block owns contiguous row chunk; per
//    overlapping segment a pure ldcs->FMA stream (4-row unroll); flush via
//    cross-warp smem reduction, warp 0 issues the atomics.
// ---------------------------------------------------------------------------
#define ACC4(v)                                   \
    s0 += (v).x; q0 = fmaf((v).x, (v).x, q0);     \
    s1 += (v).y; q1 = fmaf((v).y, (v).y, q1);     \
    s2 += (v).z; q2 = fmaf((v).z, (v).z, q2);     \
    s3 += (v).w; q3 = fmaf((v).w, (v).w, q3);

__global__ void dogn_stats(const float4* __restrict__ data,
                           int n, int rows_per_block) {
    __shared__ int   sb[BMAX + 1];
    __shared__ int   sB;
    __shared__ float red[8 * 256];   // [k][warp*32 + lane]

    if (threadIdx.x == 0) sB = g_nseg;
    __syncthreads();
    int B = sB;
    for (int j = threadIdx.x; j <= B; j += blockDim.x) sb[j] = g_bounds[j];
    __syncthreads();

    const int tid  = threadIdx.x;
    const int lane = tid & 31;
    const int rsub = tid >> 5;
    int r0 = blockIdx.x * rows_per_block;
    int r1 = r0 + rows_per_block;
    if (r1 > n) r1 = n;
    // No early-return: segment loop stays block-uniform for __syncthreads.

    for (int seg = 0; seg < B; seg++) {
        int a = sb[seg], e = sb[seg + 1];
        if (a < r0) a = r0;
        if (e > r1) e = r1;
        if (a >= e) continue;   // block-uniform

        float s0 = 0.f, s1 = 0.f, s2 = 0.f, s3 = 0.f;
        float q0 = 0.f, q1 = 0.f, q2 = 0.f, q3 = 0.f;

        int r = a + rsub;
        for (; r + 24 < e; r += 32) {
            const float4* p = &data[(size_t)r * 32 + lane];
            float4 v0 = __ldcs(p);
            float4 v1 = __ldcs(p + 8 * 32);
            float4 v2 = __ldcs(p + 16 * 32);
            float4 v3 = __ldcs(p + 24 * 32);
            ACC4(v0) ACC4(v1) ACC4(v2) ACC4(v3)
        }
        for (; r < e; r += 8) {
            float4 v = __ldcs(&data[(size_t)r * 32 + lane]);
            ACC4(v)
        }

        red[0 * 256 + tid] = s0;
        red[1 * 256 + tid] = s1;
        red[2 * 256 + tid] = s2;
        red[3 * 256 + tid] = s3;
        red[4 * 256 + tid] = q0;
        red[5 * 256 + tid] = q1;
        red[6 * 256 + tid] = q2;
        red[7 * 256 + tid] = q3;
        __syncthreads();

        if (tid < 32) {
            double* ps = &g_sum[seg * C_CH + tid * 4];
            double* pq = &g_sqs[seg * C_CH + tid * 4];
#pragma unroll
            for (int k = 0; k < 4; k++) {
                float vs = 0.f, vq = 0.f;
#pragma unroll
                for (int w = 0; w < 8; w++) {
                    vs += red[k * 256 + w * 32 + tid];
                    vq += red[(k + 4) * 256 + w * 32 + tid];
                }
                atomicAdd(ps + k, (double)vs);
                atomicAdd(pq + k, (double)vq);
            }
        }
        __syncthreads();
    }
}

// ---------------------------------------------------------------------------
// 2) finalize: one block per batch, 32 threads = 32 groups.
// ---------------------------------------------------------------------------
__global__ void dogn_finalize(const float* __restrict__ w,
                              const float* __restrict__ bias) {
    int b = blockIdx.x;
    if (b >= g_nseg) return;
    int g = threadIdx.x;

    int nb = g_bounds[b + 1] - g_bounds[b];
    double ic = 1.0 / (4.0 * (double)nb + (double)EPSF);

    double T1 = 0.0, T2 = 0.0;
#pragma unroll
    for (int k = 0; k < 4; k++) {
        T1 += g_sum[b * C_CH + g * 4 + k];
        T2 += g_sqs[b * C_CH + g * 4 + k];
    }
    double m   = T1 * ic;
    double var = (T2 - 2.0 * m * T1 + 4.0 * (double)nb * m * m) * ic;
    double is  = 1.0 / sqrt(var + (double)EPSF);

    float4 sc, sh;
    float wv, bv;
    wv = __ldg(&w[g * 4 + 0]); bv = __ldg(&bias[g * 4 + 0]);
    sc.x = (float)(is * wv);   sh.x = (float)(bv - m * is * wv);
    wv = __ldg(&w[g * 4 + 1]); bv = __ldg(&bias[g * 4 + 1]);
    sc.y = (float)(is * wv);   sh.y = (float)(bv - m * is * wv);
    wv = __ldg(&w[g * 4 + 2]); bv = __ldg(&bias[g * 4 + 2]);
    sc.z = (float)(is * wv);   sh.z = (float)(bv - m * is * wv);
    wv = __ldg(&w[g * 4 + 3]); bv = __ldg(&bias[g * 4 + 3]);
    sc.w = (float)(is * wv);   sh.w = (float)(bv - m * is * wv);

    g_scale[b * NGROUP + g] = sc;
    g_shift[b * NGROUP + g] = sh;
}

// ---------------------------------------------------------------------------
// 3) normalize: EXACT R9 WIN body — inline index arithmetic, no launch bounds.
// ---------------------------------------------------------------------------
__global__ void dogn_norm(const float4* __restrict__ data,
                          float4* __restrict__ out,
                          int n, int rows_per_block) {
    __shared__ int sb[BMAX + 1];
    __shared__ int sB;
    if (threadIdx.x == 0) sB = g_nseg;
    __syncthreads();
    int B = sB;
    for (int j = threadIdx.x; j <= B; j += blockDim.x) sb[j] = g_bounds[j];
    __syncthreads();

    const int lane = threadIdx.x & 31;
    const int rsub = threadIdx.x >> 5;
    int r0 = blockIdx.x * rows_per_block;
    int r1 = r0 + rows_per_block;
    if (r1 > n) r1 = n;
    if (r0 >= r1) return;

    for (int seg = 0; seg < B; seg++) {
        int a = sb[seg], e = sb[seg + 1];
        if (a < r0) a = r0;
        if (e > r1) e = r1;
        if (a >= e) continue;

        float4 sc = g_scale[seg * NGROUP + lane];
        float4 sh = g_shift[seg * NGROUP + lane];

        int r = a + rsub;
        for (; r + 24 < e; r += 32) {
            float4 v0 = __ldcs(&data[(size_t)r * 32 + lane]);
            float4 v1 = __ldcs(&data[(size_t)(r + 8) * 32 + lane]);
            float4 v2 = __ldcs(&data[(size_t)(r + 16) * 32 + lane]);
            float4 v3 = __ldcs(&data[(size_t)(r + 24) * 32 + lane]);
            v0.x = fmaf(v0.x, sc.x, sh.x);
            v0.y = fmaf(v0.y, sc.y, sh.y);
            v0.z = fmaf(v0.z, sc.z, sh.z);
            v0.w = fmaf(v0.w, sc.w, sh.w);
            v1.x = fmaf(v1.x, sc.x, sh.x);
            v1.y = fmaf(v1.y, sc.y, sh.y);
            v1.z = fmaf(v1.z, sc.z, sh.z);
            v1.w = fmaf(v1.w, sc.w, sh.w);
            v2.x = fmaf(v2.x, sc.x, sh.x);
            v2.y = fmaf(v2.y, sc.y, sh.y);
            v2.z = fmaf(v2.z, sc.z, sh.z);
            v2.w = fmaf(v2.w, sc.w, sh.w);
            v3.x = fmaf(v3.x, sc.x, sh.x);
            v3.y = fmaf(v3.y, sc.y, sh.y);
            v3.z = fmaf(v3.z, sc.z, sh.z);
            v3.w = fmaf(v3.w, sc.w, sh.w);
            __stcs(&out[(size_t)r * 32 + lane], v0);
            __stcs(&out[(size_t)(r + 8) * 32 + lane], v1);
            __stcs(&out[(size_t)(r + 16) * 32 + lane], v2);
            __stcs(&out[(size_t)(r + 24) * 32 + lane], v3);
        }
        for (; r < e; r += 8) {
            float4 v = __ldcs(&data[(size_t)r * 32 + lane]);
            v.x = fmaf(v.x, sc.x, sh.x);
            v.y = fmaf(v.y, sc.y, sh.y);
            v.z = fmaf(v.z, sc.z, sh.z);
            v.w = fmaf(v.w, sc.w, sh.w);
            __stcs(&out[(size_t)r * 32 + lane], v);
        }
    }
}

// ---------------------------------------------------------------------------
extern "C" void kernel_launch(void* const* d_in, const int* in_sizes, int n_in,
                              void* d_out, int out_size) {
    const float* data = (const float*)d_in[0];
    const float* w    = (const float*)d_in[1];
    const float* bias = (const float*)d_in[2];
    const int*   bid  = (const int*)d_in[3];
    const int*   bsz  = (const int*)d_in[4];

    int n = in_sizes[0] / C_CH;   // rows

    dogn_setup<<<17, 512>>>(bid, n, bsz);

    // stats: 2 waves of half-size chunks — shrink the slow-CTA tail.
    // (atomic count stays low: smem-reduced flush = 256 atomics/block-seg)
    const int SGRID = 2368;
    int srpb = (n + SGRID - 1) / SGRID;
    dogn_stats<<<SGRID, 256>>>((const float4*)data, n, srpb);

    dogn_finalize<<<BMAX, 32>>>(w, bias);

    // norm: unchanged from R9 WIN
    const int NGRID = 1184;
    int nrpb = (n + NGRID - 1) / NGRID;
    dogn_norm<<<NGRID, 256>>>((const float4*)data, (float4*)d_out, n, nrpb);
}

// round 11
// speedup vs baseline: 1.8303x; 1.0010x over previous
#include <cuda_runtime.h>

#define C_CH   128
#define NGROUP 32
#define CPG    4
#define BMAX   64
#define EPSF   1e-5f

// Scratch (no allocations allowed)
__device__ double g_sum[BMAX * C_CH];
__device__ double g_sqs[BMAX * C_CH];
__device__ int    g_bounds[BMAX + 1];
__device__ int    g_nseg;
__device__ float4 g_scale[BMAX * NGROUP];
__device__ float4 g_shift[BMAX * NGROUP];

// ---------------------------------------------------------------------------
// 0) setup: zero accumulators + segment bounds by binary search.
// ---------------------------------------------------------------------------
__global__ void dogn_setup(const int* __restrict__ bid, int n,
                           const int* __restrict__ bsz_ptr) {
    if (blockIdx.x < 16) {
        int i = blockIdx.x * 512 + threadIdx.x;
        if (i < BMAX * C_CH) {
            g_sum[i] = 0.0;
            g_sqs[i] = 0.0;
        }
    } else {
        int B = __ldg(bsz_ptr);
        if (B > BMAX) B = BMAX;
        int t = threadIdx.x;
        if (t == 0) g_nseg = B;
        if (t <= B) {
            int lo = 0, hi = n;
            while (lo < hi) {
                int mid = (lo + hi) >> 1;
                if (__ldg(&bid[mid]) < t) lo = mid + 1;
                else hi = mid;
            }
            g_bounds[t] = lo;
        }
    }
}

// ---------------------------------------------------------------------------
// 1) stats: block owns contiguous row chunk; per overlapping segment a pure
//    ldcs->FMA stream (4-row unroll); flush via cross-warp smem reduction,
//    warp 0 issues the atomics.
// ---------------------------------------------------------------------------
#define ACC4(v)                                   \
    s0 += (v).x; q0 = fmaf((v).x, (v).x, q0);     \
    s1 += (v).y; q1 = fmaf((v).y, (v).y, q1);     \
    s2 += (v).z; q2 = fmaf((v).z, (v).z, q2);     \
    s3 += (v).w; q3 = fmaf((v).w, (v).w, q3);

__global__ void dogn_stats(const float4* __restrict__ data,
                           int n, int rows_per_block) {
    __shared__ int   sb[BMAX + 1];
    __shared__ int   sB;
    __shared__ float red[8 * 256];   // [k][warp*32 + lane]

    if (threadIdx.x == 0) sB = g_nseg;
    __syncthreads();
    int B = sB;
    for (int j = threadIdx.x; j <= B; j += blockDim.x) sb[j] = g_bounds[j];
    __syncthreads();

    const int tid  = threadIdx.x;
    const int lane = tid & 31;
    const int rsub = tid >> 5;
    int r0 = blockIdx.x * rows_per_block;
    int r1 = r0 + rows_per_block;
    if (r1 > n) r1 = n;
    // No early-return: segment loop stays block-uniform for __syncthreads.

    for (int seg = 0; seg < B; seg++) {
        int a = sb[seg], e = sb[seg + 1];
        if (a < r0) a = r0;
        if (e > r1) e = r1;
        if (a >= e) continue;   // block-uniform

        float s0 = 0.f, s1 = 0.f, s2 = 0.f, s3 = 0.f;
        float q0 = 0.f, q1 = 0.f, q2 = 0.f, q3 = 0.f;

        int r = a + rsub;
        for (; r + 24 < e; r += 32) {
            const float4* p = &data[(size_t)r * 32 + lane];
            float4 v0 = __ldcs(p);
            float4 v1 = __ldcs(p + 8 * 32);
            float4 v2 = __ldcs(p + 16 * 32);
            float4 v3 = __ldcs(p + 24 * 32);
            ACC4(v0) ACC4(v1) ACC4(v2) ACC4(v3)
        }
        for (; r < e; r += 8) {
            float4 v = __ldcs(&data[(size_t)r * 32 + lane]);
            ACC4(v)
        }

        red[0 * 256 + tid] = s0;
        red[1 * 256 + tid] = s1;
        red[2 * 256 + tid] = s2;
        red[3 * 256 + tid] = s3;
        red[4 * 256 + tid] = q0;
        red[5 * 256 + tid] = q1;
        red[6 * 256 + tid] = q2;
        red[7 * 256 + tid] = q3;
        __syncthreads();

        if (tid < 32) {
            double* ps = &g_sum[seg * C_CH + tid * 4];
            double* pq = &g_sqs[seg * C_CH + tid * 4];
#pragma unroll
            for (int k = 0; k < 4; k++) {
                float vs = 0.f, vq = 0.f;
#pragma unroll
                for (int w = 0; w < 8; w++) {
                    vs += red[k * 256 + w * 32 + tid];
                    vq += red[(k + 4) * 256 + w * 32 + tid];
                }
                atomicAdd(ps + k, (double)vs);
                atomicAdd(pq + k, (double)vq);
            }
        }
        __syncthreads();
    }
}

// ---------------------------------------------------------------------------
// 2) finalize: one block per batch, 32 threads = 32 groups.
// ---------------------------------------------------------------------------
__global__ void dogn_finalize(const float* __restrict__ w,
                              const float* __restrict__ bias) {
    int b = blockIdx.x;
    if (b >= g_nseg) return;
    int g = threadIdx.x;

    int nb = g_bounds[b + 1] - g_bounds[b];
    double ic = 1.0 / (4.0 * (double)nb + (double)EPSF);

    double T1 = 0.0, T2 = 0.0;
#pragma unroll
    for (int k = 0; k < 4; k++) {
        T1 += g_sum[b * C_CH + g * 4 + k];
        T2 += g_sqs[b * C_CH + g * 4 + k];
    }
    double m   = T1 * ic;
    double var = (T2 - 2.0 * m * T1 + 4.0 * (double)nb * m * m) * ic;
    double is  = 1.0 / sqrt(var + (double)EPSF);

    float4 sc, sh;
    float wv, bv;
    wv = __ldg(&w[g * 4 + 0]); bv = __ldg(&bias[g * 4 + 0]);
    sc.x = (float)(is * wv);   sh.x = (float)(bv - m * is * wv);
    wv = __ldg(&w[g * 4 + 1]); bv = __ldg(&bias[g * 4 + 1]);
    sc.y = (float)(is * wv);   sh.y = (float)(bv - m * is * wv);
    wv = __ldg(&w[g * 4 + 2]); bv = __ldg(&bias[g * 4 + 2]);
    sc.z = (float)(is * wv);   sh.z = (float)(bv - m * is * wv);
    wv = __ldg(&w[g * 4 + 3]); bv = __ldg(&bias[g * 4 + 3]);
    sc.w = (float)(is * wv);   sh.w = (float)(bv - m * is * wv);

    g_scale[b * NGROUP + g] = sc;
    g_shift[b * NGROUP + g] = sh;
}

// ---------------------------------------------------------------------------
// 3) normalize: EXACT R9/R10 WIN body — inline index arithmetic,
//    no launch bounds. Only the grid (chunk size) changes.
// ---------------------------------------------------------------------------
__global__ void dogn_norm(const float4* __restrict__ data,
                          float4* __restrict__ out,
                          int n, int rows_per_block) {
    __shared__ int sb[BMAX + 1];
    __shared__ int sB;
    if (threadIdx.x == 0) sB = g_nseg;
    __syncthreads();
    int B = sB;
    for (int j = threadIdx.x; j <= B; j += blockDim.x) sb[j] = g_bounds[j];
    __syncthreads();

    const int lane = threadIdx.x & 31;
    const int rsub = threadIdx.x >> 5;
    int r0 = blockIdx.x * rows_per_block;
    int r1 = r0 + rows_per_block;
    if (r1 > n) r1 = n;
    if (r0 >= r1) return;

    for (int seg = 0; seg < B; seg++) {
        int a = sb[seg], e = sb[seg + 1];
        if (a < r0) a = r0;
        if (e > r1) e = r1;
        if (a >= e) continue;

        float4 sc = g_scale[seg * NGROUP + lane];
        float4 sh = g_shift[seg * NGROUP + lane];

        int r = a + rsub;
        for (; r + 24 < e; r += 32) {
            float4 v0 = __ldcs(&data[(size_t)r * 32 + lane]);
            float4 v1 = __ldcs(&data[(size_t)(r + 8) * 32 + lane]);
            float4 v2 = __ldcs(&data[(size_t)(r + 16) * 32 + lane]);
            float4 v3 = __ldcs(&data[(size_t)(r + 24) * 32 + lane]);
            v0.x = fmaf(v0.x, sc.x, sh.x);
            v0.y = fmaf(v0.y, sc.y, sh.y);
            v0.z = fmaf(v0.z, sc.z, sh.z);
            v0.w = fmaf(v0.w, sc.w, sh.w);
            v1.x = fmaf(v1.x, sc.x, sh.x);
            v1.y = fmaf(v1.y, sc.y, sh.y);
            v1.z = fmaf(v1.z, sc.z, sh.z);
            v1.w = fmaf(v1.w, sc.w, sh.w);
            v2.x = fmaf(v2.x, sc.x, sh.x);
            v2.y = fmaf(v2.y, sc.y, sh.y);
            v2.z = fmaf(v2.z, sc.z, sh.z);
            v2.w = fmaf(v2.w, sc.w, sh.w);
            v3.x = fmaf(v3.x, sc.x, sh.x);
            v3.y = fmaf(v3.y, sc.y, sh.y);
            v3.z = fmaf(v3.z, sc.z, sh.z);
            v3.w = fmaf(v3.w, sc.w, sh.w);
            __stcs(&out[(size_t)r * 32 + lane], v0);
            __stcs(&out[(size_t)(r + 8) * 32 + lane], v1);
            __stcs(&out[(size_t)(r + 16) * 32 + lane], v2);
            __stcs(&out[(size_t)(r + 24) * 32 + lane], v3);
        }
        for (; r < e; r += 8) {
            float4 v = __ldcs(&data[(size_t)r * 32 + lane]);
            v.x = fmaf(v.x, sc.x, sh.x);
            v.y = fmaf(v.y, sc.y, sh.y);
            v.z = fmaf(v.z, sc.z, sh.z);
            v.w = fmaf(v.w, sc.w, sh.w);
            __stcs(&out[(size_t)r * 32 + lane], v);
        }
    }
}

// ---------------------------------------------------------------------------
extern "C" void kernel_launch(void* const* d_in, const int* in_sizes, int n_in,
                              void* d_out, int out_size) {
    const float* data = (const float*)d_in[0];
    const float* w    = (const float*)d_in[1];
    const float* bias = (const float*)d_in[2];
    const int*   bid  = (const int*)d_in[3];
    const int*   bsz  = (const int*)d_in[4];

    int n = in_sizes[0] / C_CH;   // rows

    dogn_setup<<<17, 512>>>(bid, n, bsz);

    // stats: finer chunks shrink the slow-CTA tail (validated R10);
    // smem-reduced flush keeps atomic pressure trivial.
    const int SGRID = 3552;
    int srpb = (n + SGRID - 1) / SGRID;
    dogn_stats<<<SGRID, 256>>>((const float4*)data, n, srpb);

    dogn_finalize<<<BMAX, 32>>>(w, bias);

    // norm: same wave-quantization fix — no atomics, so finer grid is free.
    const int NGRID = 2368;
    int nrpb = (n + NGRID - 1) / NGRID;
    dogn_norm<<<NGRID, 256>>>((const float4*)data, (float4*)d_out, n, nrpb);
}